// round 1
// baseline (speedup 1.0000x reference)
#include <cuda_runtime.h>
#include <cuda_bf16.h>
#include <math.h>

#define NN 50000
#define DD 128
#define HH 8
#define DHH 16
#define EE 800000
#define DFF 512

// ---------------- scratch (static device globals; no allocation) ----------------
__device__ float g_z[NN * DD];        // per-head projection, [N,128]
__device__ float g_wt[DD * DD];       // W_fc transposed to [d_in, h*16+k]
__device__ float g_el[NN * HH];
__device__ float g_er[NN * HH];
__device__ float g_w[EE * HH];        // exp(leaky(..)) per edge/head
__device__ float g_s[NN * HH];        // softmax denominators
__device__ float g_hagg[NN * DD];     // aggregated messages
__device__ float g_hres[NN * DD];     // x + elu(h)
__device__ float g_ln[NN * DD];       // layernorm output
__device__ float g_inter[NN * DFF];   // FFN intermediate

// ---------------- zero init ----------------
__global__ void zero_kernel() {
    int i = blockIdx.x * blockDim.x + threadIdx.x;
    int stride = gridDim.x * blockDim.x;
    for (int j = i; j < NN * DD; j += stride) g_hagg[j] = 0.f;
    for (int j = i; j < NN * HH; j += stride) g_s[j] = 0.f;
}

// ---------------- W_fc transpose: [H,D,DH] -> [D, H*DH] ----------------
__global__ void transpose_wfc(const float* __restrict__ wfc) {
    int idx = blockIdx.x * blockDim.x + threadIdx.x;
    if (idx >= DD * DD) return;
    int h = idx >> 11;            // /2048
    int d = (idx >> 4) & 127;
    int k = idx & 15;
    g_wt[d * DD + h * DHH + k] = wfc[idx];
}

// ---------------- tiled fp32 GEMM, 128x128 tile, 8x8 microtile ----------------
// EPI: 0 = plain store, 1 = relu(acc + bias), 2 = acc + bias + res
template <int EPI>
__global__ void __launch_bounds__(256) sgemm_kernel(
    const float* __restrict__ A, const float* __restrict__ B, float* __restrict__ C,
    int M, int Nn, int K, const float* __restrict__ bias, const float* __restrict__ res)
{
    __shared__ float As[32][132];
    __shared__ float Bs[32][128];
    const int tid = threadIdx.x;
    const int m0 = blockIdx.x * 128;
    const int n0 = blockIdx.y * 128;
    const int tx = tid & 15;      // 16 groups over M (8 rows each)
    const int ty = tid >> 4;      // 16 groups over N (8 cols each)
    const int tk = tid & 31, tm = tid >> 5;
    const int tn = (tid & 31) * 4, tkb = tid >> 5;

    float acc[8][8];
#pragma unroll
    for (int i = 0; i < 8; ++i)
#pragma unroll
        for (int j = 0; j < 8; ++j) acc[i][j] = 0.f;

    for (int k0 = 0; k0 < K; k0 += 32) {
#pragma unroll
        for (int i = 0; i < 16; ++i) {
            int m = i * 8 + tm;
            As[tk][m] = (m0 + m < M) ? A[(m0 + m) * K + k0 + tk] : 0.f;
        }
#pragma unroll
        for (int i = 0; i < 4; ++i) {
            int k = i * 8 + tkb;
            *(float4*)&Bs[k][tn] = *(const float4*)&B[(k0 + k) * Nn + n0 + tn];
        }
        __syncthreads();
#pragma unroll
        for (int k = 0; k < 32; ++k) {
            float a[8], b[8];
            *(float4*)(a)     = *(float4*)&As[k][tx * 8];
            *(float4*)(a + 4) = *(float4*)&As[k][tx * 8 + 4];
            *(float4*)(b)     = *(float4*)&Bs[k][ty * 8];
            *(float4*)(b + 4) = *(float4*)&Bs[k][ty * 8 + 4];
#pragma unroll
            for (int i = 0; i < 8; ++i)
#pragma unroll
                for (int j = 0; j < 8; ++j) acc[i][j] = fmaf(a[i], b[j], acc[i][j]);
        }
        __syncthreads();
    }

#pragma unroll
    for (int i = 0; i < 8; ++i) {
        int m = m0 + tx * 8 + i;
        if (m >= M) continue;
#pragma unroll
        for (int j = 0; j < 8; ++j) {
            int n = n0 + ty * 8 + j;
            float v = acc[i][j];
            if (EPI == 1) { v += bias[n]; v = fmaxf(v, 0.f); }
            if (EPI == 2) { v += bias[n] + res[m * Nn + n]; }
            C[m * Nn + n] = v;
        }
    }
}

// ---------------- el / er per node ----------------
__global__ void eler_kernel(const float* __restrict__ a_l, const float* __restrict__ a_r) {
    int n = blockIdx.x;
    int t = threadIdx.x;   // 0..127 = h*16 + k
    float v = g_z[n * DD + t];
    float pl = v * a_l[t];
    float pr = v * a_r[t];
#pragma unroll
    for (int o = 8; o >= 1; o >>= 1) {
        pl += __shfl_down_sync(0xffffffffu, pl, o, 16);
        pr += __shfl_down_sync(0xffffffffu, pr, o, 16);
    }
    if ((t & 15) == 0) {
        int h = t >> 4;
        g_el[n * HH + h] = pl;
        g_er[n * HH + h] = pr;
    }
}

// ---------------- edge pass 1: w = exp(leaky(el+er)); s[dst,h] += w ----------------
__global__ void edge_w_kernel(const int* __restrict__ esrc, const int* __restrict__ edst) {
    int idx = blockIdx.x * blockDim.x + threadIdx.x;
    if (idx >= EE * HH) return;
    int e = idx >> 3;
    int h = idx & 7;
    int s = esrc[e], d = edst[e];
    float ev = g_el[s * HH + h] + g_er[d * HH + h];
    ev = (ev > 0.f) ? ev : 0.01f * ev;
    float w = expf(ev);
    g_w[idx] = w;
    atomicAdd(&g_s[d * HH + h], w);
}

// ---------------- edge pass 2: h[dst,d] += (w/s) * z[src,d] ----------------
__global__ void edge_agg_kernel(const int* __restrict__ esrc, const int* __restrict__ edst) {
    int idx = blockIdx.x * blockDim.x + threadIdx.x;  // over E*128
    int e = idx >> 7;
    int d = idx & 127;
    if (e >= EE) return;
    int h = d >> 4;
    int s = esrc[e], dst = edst[e];
    float denom = fmaxf(g_s[dst * HH + h], 1e-9f);
    float alpha = g_w[(e << 3) + h] / denom;
    atomicAdd(&g_hagg[dst * DD + d], alpha * g_z[s * DD + d]);
}

// ---------------- elu + residual + LayerNorm (warp per node) ----------------
__global__ void ln_kernel(const float* __restrict__ x,
                          const float* __restrict__ gamma, const float* __restrict__ beta) {
    int warp = threadIdx.x >> 5;
    int lane = threadIdx.x & 31;
    int n = blockIdx.x * 8 + warp;
    if (n >= NN) return;
    float4 hv = ((const float4*)(g_hagg + n * DD))[lane];
    float4 xv = ((const float4*)(x + n * DD))[lane];
    float4 r;
    r.x = xv.x + (hv.x > 0.f ? hv.x : expm1f(hv.x));
    r.y = xv.y + (hv.y > 0.f ? hv.y : expm1f(hv.y));
    r.z = xv.z + (hv.z > 0.f ? hv.z : expm1f(hv.z));
    r.w = xv.w + (hv.w > 0.f ? hv.w : expm1f(hv.w));
    ((float4*)(g_hres + n * DD))[lane] = r;
    float sum = r.x + r.y + r.z + r.w;
    float sq = r.x * r.x + r.y * r.y + r.z * r.z + r.w * r.w;
#pragma unroll
    for (int o = 16; o >= 1; o >>= 1) {
        sum += __shfl_xor_sync(0xffffffffu, sum, o);
        sq  += __shfl_xor_sync(0xffffffffu, sq, o);
    }
    float mu = sum * (1.f / 128.f);
    float var = sq * (1.f / 128.f) - mu * mu;
    float rstd = rsqrtf(var + 1e-5f);
    float4 gv = ((const float4*)gamma)[lane];
    float4 bv = ((const float4*)beta)[lane];
    float4 o;
    o.x = (r.x - mu) * rstd * gv.x + bv.x;
    o.y = (r.y - mu) * rstd * gv.y + bv.y;
    o.z = (r.z - mu) * rstd * gv.z + bv.z;
    o.w = (r.w - mu) * rstd * gv.w + bv.w;
    ((float4*)(g_ln + n * DD))[lane] = o;
}

// ---------------- launch ----------------
extern "C" void kernel_launch(void* const* d_in, const int* in_sizes, int n_in,
                              void* d_out, int out_size) {
    const float* x      = (const float*)d_in[0];
    const float* wfc    = (const float*)d_in[1];
    const float* a_l    = (const float*)d_in[2];
    const float* a_r    = (const float*)d_in[3];
    const float* gamma  = (const float*)d_in[4];
    const float* beta   = (const float*)d_in[5];
    const float* W1     = (const float*)d_in[6];
    const float* b1     = (const float*)d_in[7];
    const float* W2     = (const float*)d_in[8];
    const float* b2     = (const float*)d_in[9];
    const int* esrc     = (const int*)d_in[10];
    const int* edst     = (const int*)d_in[11];
    float* out          = (float*)d_out;

    float *p_z, *p_wt, *p_ln, *p_inter, *p_hres;
    cudaGetSymbolAddress((void**)&p_z, g_z);
    cudaGetSymbolAddress((void**)&p_wt, g_wt);
    cudaGetSymbolAddress((void**)&p_ln, g_ln);
    cudaGetSymbolAddress((void**)&p_inter, g_inter);
    cudaGetSymbolAddress((void**)&p_hres, g_hres);

    zero_kernel<<<1024, 256>>>();
    transpose_wfc<<<(DD * DD + 255) / 256, 256>>>(wfc);

    // z = x @ WT   [50000,128] = [50000,128] @ [128,128]
    {
        dim3 grid((NN + 127) / 128, 1);
        sgemm_kernel<0><<<grid, 256>>>(x, p_wt, p_z, NN, DD, DD, nullptr, nullptr);
    }
    eler_kernel<<<NN, 128>>>(a_l, a_r);
    edge_w_kernel<<<(EE * HH + 255) / 256, 256>>>(esrc, edst);
    edge_agg_kernel<<<(EE * DD) / 256, 256>>>(esrc, edst);
    ln_kernel<<<(NN + 7) / 8, 256>>>(x, gamma, beta);

    // inter = relu(ln @ W1 + b1)   [50000,512]
    {
        dim3 grid((NN + 127) / 128, DFF / 128);
        sgemm_kernel<1><<<grid, 256>>>(p_ln, W1, p_inter, NN, DFF, DD, b1, nullptr);
    }
    // out = inter @ W2 + b2 + hres   [50000,128]
    {
        dim3 grid((NN + 127) / 128, 1);
        sgemm_kernel<2><<<grid, 256>>>(p_inter, W2, out, NN, DD, DFF, b2, p_hres);
    }
}

// round 2
// speedup vs baseline: 1.6257x; 1.6257x over previous
#include <cuda_runtime.h>
#include <cuda_bf16.h>
#include <math.h>

#define NN 50000
#define DD 128
#define HH 8
#define DHH 16
#define EE 800000
#define DFF 512

// ---------------- scratch (static device globals; no allocation) ----------------
__device__ float g_z[NN * DD];        // per-head projection, [N,128]
__device__ float g_wt[DD * DD];       // W_fc transposed to [d_in, h*16+k]
__device__ float g_el[NN * HH];
__device__ float g_er[NN * HH];
__device__ float g_w[EE * HH];        // exp(leaky(..)) per edge/head
__device__ float g_s[NN * HH];        // softmax denominators
__device__ float g_hagg[NN * DD];     // aggregated messages
__device__ float g_hres[NN * DD];     // x + elu(h)
__device__ float g_ln[NN * DD];       // layernorm output
__device__ float g_inter[NN * DFF];   // FFN intermediate

// ---------------- zero init ----------------
__global__ void zero_kernel() {
    int i = blockIdx.x * blockDim.x + threadIdx.x;
    int stride = gridDim.x * blockDim.x;
    for (int j = i; j < NN * DD; j += stride) g_hagg[j] = 0.f;
    for (int j = i; j < NN * HH; j += stride) g_s[j] = 0.f;
}

// ---------------- W_fc transpose: [H,D,DH] -> [D, H*DH] ----------------
__global__ void transpose_wfc(const float* __restrict__ wfc) {
    int idx = blockIdx.x * blockDim.x + threadIdx.x;
    if (idx >= DD * DD) return;
    int h = idx >> 11;            // /2048
    int d = (idx >> 4) & 127;
    int k = idx & 15;
    g_wt[d * DD + h * DHH + k] = wfc[idx];
}

// ---------------- tf32 helpers ----------------
__device__ __forceinline__ unsigned f2tf(float f) {
    unsigned u;
    asm("cvt.rna.tf32.f32 %0, %1;" : "=r"(u) : "f"(f));
    return u;
}
__device__ __forceinline__ uint4 f2tf4(float4 v) {
    uint4 r;
    r.x = f2tf(v.x); r.y = f2tf(v.y); r.z = f2tf(v.z); r.w = f2tf(v.w);
    return r;
}
__device__ __forceinline__ void mma_tf32(float* c, const unsigned* a, const unsigned* b) {
    asm volatile(
        "mma.sync.aligned.m16n8k8.row.col.f32.tf32.tf32.f32 "
        "{%0,%1,%2,%3}, {%4,%5,%6,%7}, {%8,%9}, {%0,%1,%2,%3};"
        : "+f"(c[0]), "+f"(c[1]), "+f"(c[2]), "+f"(c[3])
        : "r"(a[0]), "r"(a[1]), "r"(a[2]), "r"(a[3]), "r"(b[0]), "r"(b[1]));
}

// ---------------- tf32 tensor-core GEMM, 128x128 tile ----------------
// C[M,Nn] = A[M,K] @ B[K,Nn]; Nn multiple of 128, K multiple of 32.
// 256 threads = 8 warps (2 M x 4 N), warp tile 64x32, mma m16n8k8.
// EPI: 0 = plain store, 1 = relu(acc + bias), 2 = acc + bias + res
template <int EPI>
__global__ void __launch_bounds__(256) tgemm_kernel(
    const float* __restrict__ A, const float* __restrict__ B, float* __restrict__ C,
    int M, int Nn, int K, const float* __restrict__ bias, const float* __restrict__ res)
{
    __shared__ unsigned As[128][36];   // [m][k], pad 36 -> conflict-free frag loads
    __shared__ unsigned Bs[32][136];   // [k][n], pad 136 -> conflict-free frag loads

    const int tid = threadIdx.x;
    const int lane = tid & 31;
    const int wid = tid >> 5;
    const int wm = wid >> 2;          // 0..1
    const int wn = wid & 3;           // 0..3
    const int lr = lane >> 2;         // 0..7
    const int lc = lane & 3;          // 0..3
    const int m0 = blockIdx.x * 128;
    const int n0 = blockIdx.y * 128;

    float acc[4][4][4];
#pragma unroll
    for (int i = 0; i < 4; ++i)
#pragma unroll
        for (int j = 0; j < 4; ++j)
#pragma unroll
            for (int r = 0; r < 4; ++r) acc[i][j][r] = 0.f;

    for (int k0 = 0; k0 < K; k0 += 32) {
        // A tile: 128x32 floats, 4 float4 per thread
#pragma unroll
        for (int i = 0; i < 4; ++i) {
            int id = tid + i * 256;
            int m = id >> 3;
            int kq = id & 7;
            float4 v = make_float4(0.f, 0.f, 0.f, 0.f);
            if (m0 + m < M) v = *(const float4*)&A[(size_t)(m0 + m) * K + k0 + kq * 4];
            *(uint4*)&As[m][kq * 4] = f2tf4(v);
        }
        // B tile: 32x128 floats
#pragma unroll
        for (int i = 0; i < 4; ++i) {
            int id = tid + i * 256;
            int k = id >> 5;
            int nq = id & 31;
            float4 v = *(const float4*)&B[(size_t)(k0 + k) * Nn + n0 + nq * 4];
            *(uint4*)&Bs[k][nq * 4] = f2tf4(v);
        }
        __syncthreads();

#pragma unroll
        for (int k8 = 0; k8 < 32; k8 += 8) {
            unsigned af[4][4], bf[4][2];
#pragma unroll
            for (int mt = 0; mt < 4; ++mt) {
                int rm = wm * 64 + mt * 16 + lr;
                af[mt][0] = As[rm][k8 + lc];
                af[mt][1] = As[rm + 8][k8 + lc];
                af[mt][2] = As[rm][k8 + lc + 4];
                af[mt][3] = As[rm + 8][k8 + lc + 4];
            }
#pragma unroll
            for (int nt = 0; nt < 4; ++nt) {
                int nb = wn * 32 + nt * 8 + lr;
                bf[nt][0] = Bs[k8 + lc][nb];
                bf[nt][1] = Bs[k8 + lc + 4][nb];
            }
#pragma unroll
            for (int mt = 0; mt < 4; ++mt)
#pragma unroll
                for (int nt = 0; nt < 4; ++nt)
                    mma_tf32(acc[mt][nt], af[mt], bf[nt]);
        }
        __syncthreads();
    }

    // epilogue
#pragma unroll
    for (int mt = 0; mt < 4; ++mt) {
#pragma unroll
        for (int nt = 0; nt < 4; ++nt) {
            int row = m0 + wm * 64 + mt * 16 + lr;
            int col = n0 + wn * 32 + nt * 8 + 2 * lc;
            float c0 = acc[mt][nt][0], c1 = acc[mt][nt][1];
            float c2 = acc[mt][nt][2], c3 = acc[mt][nt][3];
            if (EPI == 1) {
                float b0 = bias[col], b1 = bias[col + 1];
                c0 = fmaxf(c0 + b0, 0.f); c1 = fmaxf(c1 + b1, 0.f);
                c2 = fmaxf(c2 + b0, 0.f); c3 = fmaxf(c3 + b1, 0.f);
            }
            if (EPI == 2) {
                float b0 = bias[col], b1 = bias[col + 1];
                if (row < M) {
                    c0 += b0 + res[(size_t)row * Nn + col];
                    c1 += b1 + res[(size_t)row * Nn + col + 1];
                }
                if (row + 8 < M) {
                    c2 += b0 + res[(size_t)(row + 8) * Nn + col];
                    c3 += b1 + res[(size_t)(row + 8) * Nn + col + 1];
                }
            }
            if (row < M)     *(float2*)&C[(size_t)row * Nn + col]       = make_float2(c0, c1);
            if (row + 8 < M) *(float2*)&C[(size_t)(row + 8) * Nn + col] = make_float2(c2, c3);
        }
    }
}

// ---------------- el / er per node ----------------
__global__ void eler_kernel(const float* __restrict__ a_l, const float* __restrict__ a_r) {
    int n = blockIdx.x;
    int t = threadIdx.x;   // 0..127 = h*16 + k
    float v = g_z[n * DD + t];
    float pl = v * a_l[t];
    float pr = v * a_r[t];
#pragma unroll
    for (int o = 8; o >= 1; o >>= 1) {
        pl += __shfl_down_sync(0xffffffffu, pl, o, 16);
        pr += __shfl_down_sync(0xffffffffu, pr, o, 16);
    }
    if ((t & 15) == 0) {
        int h = t >> 4;
        g_el[n * HH + h] = pl;
        g_er[n * HH + h] = pr;
    }
}

// ---------------- edge pass 1: w = exp(leaky(el+er)); s[dst,h] += w ----------------
__global__ void edge_w_kernel(const int* __restrict__ esrc, const int* __restrict__ edst) {
    int idx = blockIdx.x * blockDim.x + threadIdx.x;
    if (idx >= EE * HH) return;
    int e = idx >> 3;
    int h = idx & 7;
    int s = esrc[e], d = edst[e];
    float ev = g_el[s * HH + h] + g_er[d * HH + h];
    ev = (ev > 0.f) ? ev : 0.01f * ev;
    float w = expf(ev);
    g_w[idx] = w;
    atomicAdd(&g_s[d * HH + h], w);
}

// ---------------- edge pass 2: h[dst,d] += (w/s) * z[src,d] ----------------
__global__ void edge_agg_kernel(const int* __restrict__ esrc, const int* __restrict__ edst) {
    int idx = blockIdx.x * blockDim.x + threadIdx.x;  // over E*128
    int e = idx >> 7;
    int d = idx & 127;
    if (e >= EE) return;
    int h = d >> 4;
    int s = esrc[e], dst = edst[e];
    float denom = fmaxf(g_s[dst * HH + h], 1e-9f);
    float alpha = g_w[(e << 3) + h] / denom;
    atomicAdd(&g_hagg[dst * DD + d], alpha * g_z[s * DD + d]);
}

// ---------------- elu + residual + LayerNorm (warp per node) ----------------
__global__ void ln_kernel(const float* __restrict__ x,
                          const float* __restrict__ gamma, const float* __restrict__ beta) {
    int warp = threadIdx.x >> 5;
    int lane = threadIdx.x & 31;
    int n = blockIdx.x * 8 + warp;
    if (n >= NN) return;
    float4 hv = ((const float4*)(g_hagg + n * DD))[lane];
    float4 xv = ((const float4*)(x + n * DD))[lane];
    float4 r;
    r.x = xv.x + (hv.x > 0.f ? hv.x : expm1f(hv.x));
    r.y = xv.y + (hv.y > 0.f ? hv.y : expm1f(hv.y));
    r.z = xv.z + (hv.z > 0.f ? hv.z : expm1f(hv.z));
    r.w = xv.w + (hv.w > 0.f ? hv.w : expm1f(hv.w));
    ((float4*)(g_hres + n * DD))[lane] = r;
    float sum = r.x + r.y + r.z + r.w;
    float sq = r.x * r.x + r.y * r.y + r.z * r.z + r.w * r.w;
#pragma unroll
    for (int o = 16; o >= 1; o >>= 1) {
        sum += __shfl_xor_sync(0xffffffffu, sum, o);
        sq  += __shfl_xor_sync(0xffffffffu, sq, o);
    }
    float mu = sum * (1.f / 128.f);
    float var = sq * (1.f / 128.f) - mu * mu;
    float rstd = rsqrtf(var + 1e-5f);
    float4 gv = ((const float4*)gamma)[lane];
    float4 bv = ((const float4*)beta)[lane];
    float4 o;
    o.x = (r.x - mu) * rstd * gv.x + bv.x;
    o.y = (r.y - mu) * rstd * gv.y + bv.y;
    o.z = (r.z - mu) * rstd * gv.z + bv.z;
    o.w = (r.w - mu) * rstd * gv.w + bv.w;
    ((float4*)(g_ln + n * DD))[lane] = o;
}

// ---------------- launch ----------------
extern "C" void kernel_launch(void* const* d_in, const int* in_sizes, int n_in,
                              void* d_out, int out_size) {
    const float* x      = (const float*)d_in[0];
    const float* wfc    = (const float*)d_in[1];
    const float* a_l    = (const float*)d_in[2];
    const float* a_r    = (const float*)d_in[3];
    const float* gamma  = (const float*)d_in[4];
    const float* beta   = (const float*)d_in[5];
    const float* W1     = (const float*)d_in[6];
    const float* b1     = (const float*)d_in[7];
    const float* W2     = (const float*)d_in[8];
    const float* b2     = (const float*)d_in[9];
    const int* esrc     = (const int*)d_in[10];
    const int* edst     = (const int*)d_in[11];
    float* out          = (float*)d_out;

    float *p_z, *p_wt, *p_ln, *p_inter, *p_hres;
    cudaGetSymbolAddress((void**)&p_z, g_z);
    cudaGetSymbolAddress((void**)&p_wt, g_wt);
    cudaGetSymbolAddress((void**)&p_ln, g_ln);
    cudaGetSymbolAddress((void**)&p_inter, g_inter);
    cudaGetSymbolAddress((void**)&p_hres, g_hres);

    zero_kernel<<<1024, 256>>>();
    transpose_wfc<<<(DD * DD + 255) / 256, 256>>>(wfc);

    // z = x @ WT   [50000,128] = [50000,128] @ [128,128]
    {
        dim3 grid((NN + 127) / 128, 1);
        tgemm_kernel<0><<<grid, 256>>>(x, p_wt, p_z, NN, DD, DD, nullptr, nullptr);
    }
    eler_kernel<<<NN, 128>>>(a_l, a_r);
    edge_w_kernel<<<(EE * HH + 255) / 256, 256>>>(esrc, edst);
    edge_agg_kernel<<<(EE * DD) / 256, 256>>>(esrc, edst);
    ln_kernel<<<(NN + 7) / 8, 256>>>(x, gamma, beta);

    // inter = relu(ln @ W1 + b1)   [50000,512]
    {
        dim3 grid((NN + 127) / 128, DFF / 128);
        tgemm_kernel<1><<<grid, 256>>>(p_ln, W1, p_inter, NN, DFF, DD, b1, nullptr);
    }
    // out = inter @ W2 + b2 + hres   [50000,128]
    {
        dim3 grid((NN + 127) / 128, 1);
        tgemm_kernel<2><<<grid, 256>>>(p_inter, W2, out, NN, DD, DFF, b2, p_hres);
    }
}

// round 3
// speedup vs baseline: 3.4074x; 2.0959x over previous
#include <cuda_runtime.h>
#include <cuda_bf16.h>
#include <math.h>

#define NN 50000
#define DD 128
#define HH 8
#define DHH 16
#define EE 800000
#define DFF 512
#define NBLK_SCAN 196   // ceil(50000/256)

// ---------------- scratch (static device globals; no allocation) ----------------
__device__ float g_z[NN * DD];        // per-head projection, [N,128]
__device__ float g_wt[DD * DD];       // W_fc transposed to [d_in, h*16+k]
__device__ float g_el[NN * HH];
__device__ float g_er[NN * HH];
__device__ float g_ws[EE * HH];       // sorted-by-dst edge weights
__device__ int   g_srcs[EE];          // sorted-by-dst src indices
__device__ int   g_deg[NN];
__device__ int   g_cursor[NN];
__device__ int   g_base[NN];
__device__ int   g_bsum[256];
__device__ int   g_boff[256];
__device__ float g_hagg[NN * DD];     // aggregated messages
__device__ float g_hres[NN * DD];     // x + elu(h)
__device__ float g_ln[NN * DD];       // layernorm output
__device__ float g_inter[NN * DFF];   // FFN intermediate

// ---------------- zero init (counters only) ----------------
__global__ void zero_kernel() {
    int i = blockIdx.x * blockDim.x + threadIdx.x;
    if (i < NN) { g_deg[i] = 0; g_cursor[i] = 0; }
}

// ---------------- W_fc transpose: [H,D,DH] -> [D, H*DH] ----------------
__global__ void transpose_wfc(const float* __restrict__ wfc) {
    int idx = blockIdx.x * blockDim.x + threadIdx.x;
    if (idx >= DD * DD) return;
    int h = idx >> 11;
    int d = (idx >> 4) & 127;
    int k = idx & 15;
    g_wt[d * DD + h * DHH + k] = wfc[idx];
}

// ---------------- tf32 helpers ----------------
__device__ __forceinline__ unsigned f2tf(float f) {
    unsigned u;
    asm("cvt.rna.tf32.f32 %0, %1;" : "=r"(u) : "f"(f));
    return u;
}
__device__ __forceinline__ uint4 f2tf4(float4 v) {
    uint4 r;
    r.x = f2tf(v.x); r.y = f2tf(v.y); r.z = f2tf(v.z); r.w = f2tf(v.w);
    return r;
}
__device__ __forceinline__ void mma_tf32(float* c, const unsigned* a, const unsigned* b) {
    asm volatile(
        "mma.sync.aligned.m16n8k8.row.col.f32.tf32.tf32.f32 "
        "{%0,%1,%2,%3}, {%4,%5,%6,%7}, {%8,%9}, {%0,%1,%2,%3};"
        : "+f"(c[0]), "+f"(c[1]), "+f"(c[2]), "+f"(c[3])
        : "r"(a[0]), "r"(a[1]), "r"(a[2]), "r"(a[3]), "r"(b[0]), "r"(b[1]));
}

// ---------------- tf32 tensor-core GEMM, 128x128 tile ----------------
template <int EPI>
__global__ void __launch_bounds__(256) tgemm_kernel(
    const float* __restrict__ A, const float* __restrict__ B, float* __restrict__ C,
    int M, int Nn, int K, const float* __restrict__ bias, const float* __restrict__ res)
{
    __shared__ unsigned As[128][36];
    __shared__ unsigned Bs[32][136];

    const int tid = threadIdx.x;
    const int lane = tid & 31;
    const int wid = tid >> 5;
    const int wm = wid >> 2;
    const int wn = wid & 3;
    const int lr = lane >> 2;
    const int lc = lane & 3;
    const int m0 = blockIdx.x * 128;
    const int n0 = blockIdx.y * 128;

    float acc[4][4][4];
#pragma unroll
    for (int i = 0; i < 4; ++i)
#pragma unroll
        for (int j = 0; j < 4; ++j)
#pragma unroll
            for (int r = 0; r < 4; ++r) acc[i][j][r] = 0.f;

    for (int k0 = 0; k0 < K; k0 += 32) {
#pragma unroll
        for (int i = 0; i < 4; ++i) {
            int id = tid + i * 256;
            int m = id >> 3;
            int kq = id & 7;
            float4 v = make_float4(0.f, 0.f, 0.f, 0.f);
            if (m0 + m < M) v = *(const float4*)&A[(size_t)(m0 + m) * K + k0 + kq * 4];
            *(uint4*)&As[m][kq * 4] = f2tf4(v);
        }
#pragma unroll
        for (int i = 0; i < 4; ++i) {
            int id = tid + i * 256;
            int k = id >> 5;
            int nq = id & 31;
            float4 v = *(const float4*)&B[(size_t)(k0 + k) * Nn + n0 + nq * 4];
            *(uint4*)&Bs[k][nq * 4] = f2tf4(v);
        }
        __syncthreads();

#pragma unroll
        for (int k8 = 0; k8 < 32; k8 += 8) {
            unsigned af[4][4], bf[4][2];
#pragma unroll
            for (int mt = 0; mt < 4; ++mt) {
                int rm = wm * 64 + mt * 16 + lr;
                af[mt][0] = As[rm][k8 + lc];
                af[mt][1] = As[rm + 8][k8 + lc];
                af[mt][2] = As[rm][k8 + lc + 4];
                af[mt][3] = As[rm + 8][k8 + lc + 4];
            }
#pragma unroll
            for (int nt = 0; nt < 4; ++nt) {
                int nb = wn * 32 + nt * 8 + lr;
                bf[nt][0] = Bs[k8 + lc][nb];
                bf[nt][1] = Bs[k8 + lc + 4][nb];
            }
#pragma unroll
            for (int mt = 0; mt < 4; ++mt)
#pragma unroll
                for (int nt = 0; nt < 4; ++nt)
                    mma_tf32(acc[mt][nt], af[mt], bf[nt]);
        }
        __syncthreads();
    }

#pragma unroll
    for (int mt = 0; mt < 4; ++mt) {
#pragma unroll
        for (int nt = 0; nt < 4; ++nt) {
            int row = m0 + wm * 64 + mt * 16 + lr;
            int col = n0 + wn * 32 + nt * 8 + 2 * lc;
            float c0 = acc[mt][nt][0], c1 = acc[mt][nt][1];
            float c2 = acc[mt][nt][2], c3 = acc[mt][nt][3];
            if (EPI == 1) {
                float b0 = bias[col], b1 = bias[col + 1];
                c0 = fmaxf(c0 + b0, 0.f); c1 = fmaxf(c1 + b1, 0.f);
                c2 = fmaxf(c2 + b0, 0.f); c3 = fmaxf(c3 + b1, 0.f);
            }
            if (EPI == 2) {
                float b0 = bias[col], b1 = bias[col + 1];
                if (row < M) {
                    c0 += b0 + res[(size_t)row * Nn + col];
                    c1 += b1 + res[(size_t)row * Nn + col + 1];
                }
                if (row + 8 < M) {
                    c2 += b0 + res[(size_t)(row + 8) * Nn + col];
                    c3 += b1 + res[(size_t)(row + 8) * Nn + col + 1];
                }
            }
            if (row < M)     *(float2*)&C[(size_t)row * Nn + col]       = make_float2(c0, c1);
            if (row + 8 < M) *(float2*)&C[(size_t)(row + 8) * Nn + col] = make_float2(c2, c3);
        }
    }
}

// ---------------- el / er: one thread per (node, head) ----------------
__global__ void eler_kernel(const float* __restrict__ a_l, const float* __restrict__ a_r) {
    int idx = blockIdx.x * blockDim.x + threadIdx.x;
    if (idx >= NN * HH) return;
    int n = idx >> 3;
    int h = idx & 7;
    const float4* zp = (const float4*)&g_z[n * DD + h * DHH];
    const float4* lp = (const float4*)&a_l[h * DHH];
    const float4* rp = (const float4*)&a_r[h * DHH];
    float pl = 0.f, pr = 0.f;
#pragma unroll
    for (int q = 0; q < 4; ++q) {
        float4 z = zp[q], l = lp[q], r = rp[q];
        pl += z.x * l.x + z.y * l.y + z.z * l.z + z.w * l.w;
        pr += z.x * r.x + z.y * r.y + z.z * r.z + z.w * r.w;
    }
    g_el[idx] = pl;
    g_er[idx] = pr;
}

// ---------------- degree histogram ----------------
__global__ void deg_kernel(const int* __restrict__ edst) {
    int e = blockIdx.x * blockDim.x + threadIdx.x;
    if (e >= EE) return;
    atomicAdd(&g_deg[edst[e]], 1);
}

// ---------------- exclusive scan over deg (3 small kernels) ----------------
__global__ void scan1_kernel() {
    __shared__ int sh[256];
    int t = threadIdx.x;
    int i = blockIdx.x * 256 + t;
    int v = (i < NN) ? g_deg[i] : 0;
    sh[t] = v;
    __syncthreads();
#pragma unroll
    for (int off = 1; off < 256; off <<= 1) {
        int x = (t >= off) ? sh[t - off] : 0;
        __syncthreads();
        sh[t] += x;
        __syncthreads();
    }
    if (i < NN) g_base[i] = sh[t] - v;
    if (t == 255) g_bsum[blockIdx.x] = sh[255];
}
__global__ void scan2_kernel() {
    __shared__ int sh[256];
    int t = threadIdx.x;
    int v = (t < NBLK_SCAN) ? g_bsum[t] : 0;
    sh[t] = v;
    __syncthreads();
#pragma unroll
    for (int off = 1; off < 256; off <<= 1) {
        int x = (t >= off) ? sh[t - off] : 0;
        __syncthreads();
        sh[t] += x;
        __syncthreads();
    }
    g_boff[t] = sh[t] - v;
}
__global__ void scan3_kernel() {
    int i = blockIdx.x * blockDim.x + threadIdx.x;
    if (i < NN) g_base[i] += g_boff[i >> 8];
}

// ---------------- scatter edges into CSR slots + compute head weights ----------------
__global__ void scatter_kernel(const int* __restrict__ esrc, const int* __restrict__ edst) {
    int e = blockIdx.x * blockDim.x + threadIdx.x;
    if (e >= EE) return;
    int s = esrc[e], d = edst[e];
    int pos = g_base[d] + atomicAdd(&g_cursor[d], 1);
    g_srcs[pos] = s;
    float4 el0 = *(const float4*)&g_el[s * HH];
    float4 el1 = *(const float4*)&g_el[s * HH + 4];
    float4 er0 = *(const float4*)&g_er[d * HH];
    float4 er1 = *(const float4*)&g_er[d * HH + 4];
    float ev[8] = {el0.x + er0.x, el0.y + er0.y, el0.z + er0.z, el0.w + er0.w,
                   el1.x + er1.x, el1.y + er1.y, el1.z + er1.z, el1.w + er1.w};
    float w[8];
#pragma unroll
    for (int h = 0; h < 8; ++h) {
        float v = ev[h];
        v = (v > 0.f) ? v : 0.01f * v;
        w[h] = __expf(v);
    }
    *(float4*)&g_ws[(size_t)pos * HH]     = make_float4(w[0], w[1], w[2], w[3]);
    *(float4*)&g_ws[(size_t)pos * HH + 4] = make_float4(w[4], w[5], w[6], w[7]);
}

// ---------------- warp-per-node aggregation (no atomics) ----------------
__global__ void __launch_bounds__(256) agg_kernel() {
    int n = blockIdx.x * 8 + (threadIdx.x >> 5);
    int lane = threadIdx.x & 31;
    if (n >= NN) return;
    int start = g_base[n];
    int deg = g_deg[n];
    float4 acc = make_float4(0.f, 0.f, 0.f, 0.f);
    if (deg > 0) {
        float s0 = 0.f, s1 = 0.f, s2 = 0.f, s3 = 0.f;
        float s4 = 0.f, s5 = 0.f, s6 = 0.f, s7 = 0.f;
        for (int i = start + lane; i < start + deg; i += 32) {
            float4 wa = *(const float4*)&g_ws[(size_t)i * HH];
            float4 wb = *(const float4*)&g_ws[(size_t)i * HH + 4];
            s0 += wa.x; s1 += wa.y; s2 += wa.z; s3 += wa.w;
            s4 += wb.x; s5 += wb.y; s6 += wb.z; s7 += wb.w;
        }
#pragma unroll
        for (int o = 16; o >= 1; o >>= 1) {
            s0 += __shfl_xor_sync(0xffffffffu, s0, o);
            s1 += __shfl_xor_sync(0xffffffffu, s1, o);
            s2 += __shfl_xor_sync(0xffffffffu, s2, o);
            s3 += __shfl_xor_sync(0xffffffffu, s3, o);
            s4 += __shfl_xor_sync(0xffffffffu, s4, o);
            s5 += __shfl_xor_sync(0xffffffffu, s5, o);
            s6 += __shfl_xor_sync(0xffffffffu, s6, o);
            s7 += __shfl_xor_sync(0xffffffffu, s7, o);
        }
        int h = lane >> 2;
        float sv;
        switch (h) {
            case 0: sv = s0; break;
            case 1: sv = s1; break;
            case 2: sv = s2; break;
            case 3: sv = s3; break;
            case 4: sv = s4; break;
            case 5: sv = s5; break;
            case 6: sv = s6; break;
            default: sv = s7; break;
        }
        float inv = 1.f / fmaxf(sv, 1e-9f);
        for (int i = start; i < start + deg; ++i) {
            int src = g_srcs[i];
            float alpha = g_ws[(size_t)i * HH + h] * inv;
            float4 zv = *(const float4*)&g_z[(size_t)src * DD + lane * 4];
            acc.x = fmaf(alpha, zv.x, acc.x);
            acc.y = fmaf(alpha, zv.y, acc.y);
            acc.z = fmaf(alpha, zv.z, acc.z);
            acc.w = fmaf(alpha, zv.w, acc.w);
        }
    }
    *(float4*)&g_hagg[(size_t)n * DD + lane * 4] = acc;
}

// ---------------- elu + residual + LayerNorm (warp per node) ----------------
__global__ void ln_kernel(const float* __restrict__ x,
                          const float* __restrict__ gamma, const float* __restrict__ beta) {
    int warp = threadIdx.x >> 5;
    int lane = threadIdx.x & 31;
    int n = blockIdx.x * 8 + warp;
    if (n >= NN) return;
    float4 hv = ((const float4*)(g_hagg + n * DD))[lane];
    float4 xv = ((const float4*)(x + n * DD))[lane];
    float4 r;
    r.x = xv.x + (hv.x > 0.f ? hv.x : expm1f(hv.x));
    r.y = xv.y + (hv.y > 0.f ? hv.y : expm1f(hv.y));
    r.z = xv.z + (hv.z > 0.f ? hv.z : expm1f(hv.z));
    r.w = xv.w + (hv.w > 0.f ? hv.w : expm1f(hv.w));
    ((float4*)(g_hres + n * DD))[lane] = r;
    float sum = r.x + r.y + r.z + r.w;
    float sq = r.x * r.x + r.y * r.y + r.z * r.z + r.w * r.w;
#pragma unroll
    for (int o = 16; o >= 1; o >>= 1) {
        sum += __shfl_xor_sync(0xffffffffu, sum, o);
        sq  += __shfl_xor_sync(0xffffffffu, sq, o);
    }
    float mu = sum * (1.f / 128.f);
    float var = sq * (1.f / 128.f) - mu * mu;
    float rstd = rsqrtf(var + 1e-5f);
    float4 gv = ((const float4*)gamma)[lane];
    float4 bv = ((const float4*)beta)[lane];
    float4 o;
    o.x = (r.x - mu) * rstd * gv.x + bv.x;
    o.y = (r.y - mu) * rstd * gv.y + bv.y;
    o.z = (r.z - mu) * rstd * gv.z + bv.z;
    o.w = (r.w - mu) * rstd * gv.w + bv.w;
    ((float4*)(g_ln + n * DD))[lane] = o;
}

// ---------------- launch ----------------
extern "C" void kernel_launch(void* const* d_in, const int* in_sizes, int n_in,
                              void* d_out, int out_size) {
    const float* x      = (const float*)d_in[0];
    const float* wfc    = (const float*)d_in[1];
    const float* a_l    = (const float*)d_in[2];
    const float* a_r    = (const float*)d_in[3];
    const float* gamma  = (const float*)d_in[4];
    const float* beta   = (const float*)d_in[5];
    const float* W1     = (const float*)d_in[6];
    const float* b1     = (const float*)d_in[7];
    const float* W2     = (const float*)d_in[8];
    const float* b2     = (const float*)d_in[9];
    const int* esrc     = (const int*)d_in[10];
    const int* edst     = (const int*)d_in[11];
    float* out          = (float*)d_out;

    float *p_z, *p_wt, *p_ln, *p_inter, *p_hres;
    cudaGetSymbolAddress((void**)&p_z, g_z);
    cudaGetSymbolAddress((void**)&p_wt, g_wt);
    cudaGetSymbolAddress((void**)&p_ln, g_ln);
    cudaGetSymbolAddress((void**)&p_inter, g_inter);
    cudaGetSymbolAddress((void**)&p_hres, g_hres);

    zero_kernel<<<(NN + 255) / 256, 256>>>();
    transpose_wfc<<<(DD * DD + 255) / 256, 256>>>(wfc);

    // z = x @ WT
    {
        dim3 grid((NN + 127) / 128, 1);
        tgemm_kernel<0><<<grid, 256>>>(x, p_wt, p_z, NN, DD, DD, nullptr, nullptr);
    }
    eler_kernel<<<(NN * HH + 255) / 256, 256>>>(a_l, a_r);

    // CSR build
    deg_kernel<<<(EE + 255) / 256, 256>>>(edst);
    scan1_kernel<<<NBLK_SCAN, 256>>>();
    scan2_kernel<<<1, 256>>>();
    scan3_kernel<<<(NN + 255) / 256, 256>>>();
    scatter_kernel<<<(EE + 255) / 256, 256>>>(esrc, edst);

    agg_kernel<<<(NN + 7) / 8, 256>>>();
    ln_kernel<<<(NN + 7) / 8, 256>>>(x, gamma, beta);

    // inter = relu(ln @ W1 + b1)
    {
        dim3 grid((NN + 127) / 128, DFF / 128);
        tgemm_kernel<1><<<grid, 256>>>(p_ln, W1, p_inter, NN, DFF, DD, b1, nullptr);
    }
    // out = inter @ W2 + b2 + hres
    {
        dim3 grid((NN + 127) / 128, 1);
        tgemm_kernel<2><<<grid, 256>>>(p_inter, W2, out, NN, DD, DFF, b2, p_hres);
    }
}

// round 4
// speedup vs baseline: 3.5960x; 1.0554x over previous
#include <cuda_runtime.h>
#include <cuda_bf16.h>
#include <math.h>

#define NN 50000
#define DD 128
#define HH 8
#define DHH 16
#define EE 800000
#define DFF 512
#define NBLK_SCAN 196   // ceil(50000/256)

// ---------------- scratch (static device globals; no allocation) ----------------
__device__ float g_z[NN * DD];
__device__ float g_wt[DD * DD];
__device__ float g_el[NN * HH];
__device__ float g_er[NN * HH];
__device__ float g_ws[EE * HH];
__device__ int   g_srcs[EE];
__device__ int   g_deg[NN];
__device__ int   g_cursor[NN];
__device__ int   g_base[NN];
__device__ int   g_bsum[256];
__device__ int   g_boff[256];
__device__ float g_hagg[NN * DD];
__device__ float g_hres[NN * DD];
__device__ float g_ln[NN * DD];
__device__ float g_inter[NN * DFF];

// ---------------- zero init (counters only) ----------------
__global__ void zero_kernel() {
    int i = blockIdx.x * blockDim.x + threadIdx.x;
    if (i < NN) { g_deg[i] = 0; g_cursor[i] = 0; }
}

// ---------------- W_fc transpose: [H,D,DH] -> [D, H*DH] ----------------
__global__ void transpose_wfc(const float* __restrict__ wfc) {
    int idx = blockIdx.x * blockDim.x + threadIdx.x;
    if (idx >= DD * DD) return;
    int h = idx >> 11;
    int d = (idx >> 4) & 127;
    int k = idx & 15;
    g_wt[d * DD + h * DHH + k] = wfc[idx];
}

// ---------------- tf32 helpers ----------------
__device__ __forceinline__ unsigned f2tf(float f) {
    unsigned u;
    asm("cvt.rna.tf32.f32 %0, %1;" : "=r"(u) : "f"(f));
    return u;
}
__device__ __forceinline__ void mma_tf32(float* c, const unsigned* a, const unsigned* b) {
    asm volatile(
        "mma.sync.aligned.m16n8k8.row.col.f32.tf32.tf32.f32 "
        "{%0,%1,%2,%3}, {%4,%5,%6,%7}, {%8,%9}, {%0,%1,%2,%3};"
        : "+f"(c[0]), "+f"(c[1]), "+f"(c[2]), "+f"(c[3])
        : "r"(a[0]), "r"(a[1]), "r"(a[2]), "r"(a[3]), "r"(b[0]), "r"(b[1]));
}

// Fragment-ordered smem layouts
#define A_G_STRIDE 1028   // 8 t-groups * 32 lanes * 4 + 4 pad (bank shift 4/g)
#define B_U_STRIDE 66     // 32 lanes * 2 + 2 pad (bank shift 2/u)

// ---------------- tf32 tensor-core GEMM, 128x128 tile, fragment smem + reg dbuf ----
// EPI: 0 = plain store, 1 = relu(acc + bias), 2 = acc + bias + res
template <int EPI>
__global__ void __launch_bounds__(256) tgemm_kernel(
    const float* __restrict__ A, const float* __restrict__ B, float* __restrict__ C,
    int M, int Nn, int K, const float* __restrict__ bias, const float* __restrict__ res)
{
    __shared__ unsigned Af[4 * A_G_STRIDE];       // 4 k8-groups
    __shared__ unsigned Bf[4 * 16 * B_U_STRIDE];  // 4 k8-groups x 16 n8-groups

    const int tid = threadIdx.x;
    const int lane = tid & 31;
    const int wid = tid >> 5;
    const int wm = wid >> 2;      // 0..1
    const int wn = wid & 3;       // 0..3
    const int m0 = blockIdx.x * 128;
    const int n0 = blockIdx.y * 128;

    // loader coords
    const int a_m = tid >> 3;            // 0..31 base row (stride 32 via it)
    const int a_kq = tid & 7;            // float4 index in k
    const int b_k = tid >> 5;            // 0..7 base k (stride 8 via it)
    const int b_nq = tid & 31;           // float4 index in n

    float4 ar[4], br[4];

    auto ldg_chunk = [&](int k0) {
#pragma unroll
        for (int it = 0; it < 4; ++it) {
            int ml = a_m + it * 32;
            ar[it] = make_float4(0.f, 0.f, 0.f, 0.f);
            if (m0 + ml < M) ar[it] = *(const float4*)&A[(size_t)(m0 + ml) * K + k0 + a_kq * 4];
        }
#pragma unroll
        for (int it = 0; it < 4; ++it) {
            int kk = b_k + it * 8;
            br[it] = *(const float4*)&B[(size_t)(k0 + kk) * Nn + n0 + b_nq * 4];
        }
    };

    auto sts_chunk = [&]() {
#pragma unroll
        for (int it = 0; it < 4; ++it) {
            int ml = a_m + it * 32;
            int t = ml >> 4;
            int mr = ml & 15;
            float v[4] = {ar[it].x, ar[it].y, ar[it].z, ar[it].w};
#pragma unroll
            for (int j = 0; j < 4; ++j) {
                int kk = a_kq * 4 + j;
                int g = kk >> 3, kl = kk & 7;
                int lw = (mr & 7) * 4 + (kl & 3);
                int iw = (mr >> 3) + 2 * (kl >> 2);
                Af[g * A_G_STRIDE + t * 128 + lw * 4 + iw] = f2tf(v[j]);
            }
        }
#pragma unroll
        for (int it = 0; it < 4; ++it) {
            int kk = b_k + it * 8;
            int g = kk >> 3, kl = kk & 7;
            float v[4] = {br[it].x, br[it].y, br[it].z, br[it].w};
#pragma unroll
            for (int j = 0; j < 4; ++j) {
                int nn = b_nq * 4 + j;
                int u = nn >> 3, nl = nn & 7;
                int lw = nl * 4 + (kl & 3);
                int iw = kl >> 2;
                Bf[(g * 16 + u) * B_U_STRIDE + lw * 2 + iw] = f2tf(v[j]);
            }
        }
    };

    float acc[4][4][4];
#pragma unroll
    for (int i = 0; i < 4; ++i)
#pragma unroll
        for (int j = 0; j < 4; ++j)
#pragma unroll
            for (int r = 0; r < 4; ++r) acc[i][j][r] = 0.f;

    auto mma_chunk = [&]() {
#pragma unroll
        for (int g = 0; g < 4; ++g) {
            unsigned af[4][4], bf[4][2];
#pragma unroll
            for (int mt = 0; mt < 4; ++mt)
                *(uint4*)af[mt] = *(const uint4*)&Af[g * A_G_STRIDE + (wm * 4 + mt) * 128 + lane * 4];
#pragma unroll
            for (int nt = 0; nt < 4; ++nt)
                *(uint2*)bf[nt] = *(const uint2*)&Bf[(g * 16 + wn * 4 + nt) * B_U_STRIDE + lane * 2];
#pragma unroll
            for (int mt = 0; mt < 4; ++mt)
#pragma unroll
                for (int nt = 0; nt < 4; ++nt)
                    mma_tf32(acc[mt][nt], af[mt], bf[nt]);
        }
    };

    const int CHUNKS = K >> 5;
    ldg_chunk(0);
    sts_chunk();
    __syncthreads();
    for (int c = 1; c < CHUNKS; ++c) {
        ldg_chunk(c * 32);
        mma_chunk();
        __syncthreads();
        sts_chunk();
        __syncthreads();
    }
    mma_chunk();

    // epilogue
    const int lr = lane >> 2;
    const int lc = lane & 3;
#pragma unroll
    for (int mt = 0; mt < 4; ++mt) {
#pragma unroll
        for (int nt = 0; nt < 4; ++nt) {
            int row = m0 + wm * 64 + mt * 16 + lr;
            int col = n0 + wn * 32 + nt * 8 + 2 * lc;
            float c0 = acc[mt][nt][0], c1 = acc[mt][nt][1];
            float c2 = acc[mt][nt][2], c3 = acc[mt][nt][3];
            if (EPI == 1) {
                float b0 = bias[col], b1 = bias[col + 1];
                c0 = fmaxf(c0 + b0, 0.f); c1 = fmaxf(c1 + b1, 0.f);
                c2 = fmaxf(c2 + b0, 0.f); c3 = fmaxf(c3 + b1, 0.f);
            }
            if (EPI == 2) {
                float b0 = bias[col], b1 = bias[col + 1];
                if (row < M) {
                    c0 += b0 + res[(size_t)row * Nn + col];
                    c1 += b1 + res[(size_t)row * Nn + col + 1];
                }
                if (row + 8 < M) {
                    c2 += b0 + res[(size_t)(row + 8) * Nn + col];
                    c3 += b1 + res[(size_t)(row + 8) * Nn + col + 1];
                }
            }
            if (row < M)     *(float2*)&C[(size_t)row * Nn + col]       = make_float2(c0, c1);
            if (row + 8 < M) *(float2*)&C[(size_t)(row + 8) * Nn + col] = make_float2(c2, c3);
        }
    }
}

// ---------------- el / er: one thread per (node, head) ----------------
__global__ void eler_kernel(const float* __restrict__ a_l, const float* __restrict__ a_r) {
    int idx = blockIdx.x * blockDim.x + threadIdx.x;
    if (idx >= NN * HH) return;
    int n = idx >> 3;
    int h = idx & 7;
    const float4* zp = (const float4*)&g_z[n * DD + h * DHH];
    const float4* lp = (const float4*)&a_l[h * DHH];
    const float4* rp = (const float4*)&a_r[h * DHH];
    float pl = 0.f, pr = 0.f;
#pragma unroll
    for (int q = 0; q < 4; ++q) {
        float4 z = zp[q], l = lp[q], r = rp[q];
        pl += z.x * l.x + z.y * l.y + z.z * l.z + z.w * l.w;
        pr += z.x * r.x + z.y * r.y + z.z * r.z + z.w * r.w;
    }
    g_el[idx] = pl;
    g_er[idx] = pr;
}

// ---------------- degree histogram ----------------
__global__ void deg_kernel(const int* __restrict__ edst) {
    int e = blockIdx.x * blockDim.x + threadIdx.x;
    if (e >= EE) return;
    atomicAdd(&g_deg[edst[e]], 1);
}

// ---------------- exclusive scan over deg ----------------
__global__ void scan1_kernel() {
    __shared__ int sh[256];
    int t = threadIdx.x;
    int i = blockIdx.x * 256 + t;
    int v = (i < NN) ? g_deg[i] : 0;
    sh[t] = v;
    __syncthreads();
#pragma unroll
    for (int off = 1; off < 256; off <<= 1) {
        int x = (t >= off) ? sh[t - off] : 0;
        __syncthreads();
        sh[t] += x;
        __syncthreads();
    }
    if (i < NN) g_base[i] = sh[t] - v;
    if (t == 255) g_bsum[blockIdx.x] = sh[255];
}
__global__ void scan2_kernel() {
    __shared__ int sh[256];
    int t = threadIdx.x;
    int v = (t < NBLK_SCAN) ? g_bsum[t] : 0;
    sh[t] = v;
    __syncthreads();
#pragma unroll
    for (int off = 1; off < 256; off <<= 1) {
        int x = (t >= off) ? sh[t - off] : 0;
        __syncthreads();
        sh[t] += x;
        __syncthreads();
    }
    g_boff[t] = sh[t] - v;
}
__global__ void scan3_kernel() {
    int i = blockIdx.x * blockDim.x + threadIdx.x;
    if (i < NN) g_base[i] += g_boff[i >> 8];
}

// ---------------- scatter edges into CSR slots + compute head weights ----------------
__global__ void scatter_kernel(const int* __restrict__ esrc, const int* __restrict__ edst) {
    int e = blockIdx.x * blockDim.x + threadIdx.x;
    if (e >= EE) return;
    int s = esrc[e], d = edst[e];
    int pos = g_base[d] + atomicAdd(&g_cursor[d], 1);
    g_srcs[pos] = s;
    float4 el0 = *(const float4*)&g_el[s * HH];
    float4 el1 = *(const float4*)&g_el[s * HH + 4];
    float4 er0 = *(const float4*)&g_er[d * HH];
    float4 er1 = *(const float4*)&g_er[d * HH + 4];
    float ev[8] = {el0.x + er0.x, el0.y + er0.y, el0.z + er0.z, el0.w + er0.w,
                   el1.x + er1.x, el1.y + er1.y, el1.z + er1.z, el1.w + er1.w};
    float w[8];
#pragma unroll
    for (int h = 0; h < 8; ++h) {
        float v = ev[h];
        v = (v > 0.f) ? v : 0.01f * v;
        w[h] = __expf(v);
    }
    *(float4*)&g_ws[(size_t)pos * HH]     = make_float4(w[0], w[1], w[2], w[3]);
    *(float4*)&g_ws[(size_t)pos * HH + 4] = make_float4(w[4], w[5], w[6], w[7]);
}

// ---------------- warp-per-node aggregation (no atomics) ----------------
__global__ void __launch_bounds__(256) agg_kernel() {
    int n = blockIdx.x * 8 + (threadIdx.x >> 5);
    int lane = threadIdx.x & 31;
    if (n >= NN) return;
    int start = g_base[n];
    int deg = g_deg[n];
    float4 acc = make_float4(0.f, 0.f, 0.f, 0.f);
    if (deg > 0) {
        float s0 = 0.f, s1 = 0.f, s2 = 0.f, s3 = 0.f;
        float s4 = 0.f, s5 = 0.f, s6 = 0.f, s7 = 0.f;
        for (int i = start + lane; i < start + deg; i += 32) {
            float4 wa = *(const float4*)&g_ws[(size_t)i * HH];
            float4 wb = *(const float4*)&g_ws[(size_t)i * HH + 4];
            s0 += wa.x; s1 += wa.y; s2 += wa.z; s3 += wa.w;
            s4 += wb.x; s5 += wb.y; s6 += wb.z; s7 += wb.w;
        }
#pragma unroll
        for (int o = 16; o >= 1; o >>= 1) {
            s0 += __shfl_xor_sync(0xffffffffu, s0, o);
            s1 += __shfl_xor_sync(0xffffffffu, s1, o);
            s2 += __shfl_xor_sync(0xffffffffu, s2, o);
            s3 += __shfl_xor_sync(0xffffffffu, s3, o);
            s4 += __shfl_xor_sync(0xffffffffu, s4, o);
            s5 += __shfl_xor_sync(0xffffffffu, s5, o);
            s6 += __shfl_xor_sync(0xffffffffu, s6, o);
            s7 += __shfl_xor_sync(0xffffffffu, s7, o);
        }
        int h = lane >> 2;
        float sv;
        switch (h) {
            case 0: sv = s0; break;
            case 1: sv = s1; break;
            case 2: sv = s2; break;
            case 3: sv = s3; break;
            case 4: sv = s4; break;
            case 5: sv = s5; break;
            case 6: sv = s6; break;
            default: sv = s7; break;
        }
        float inv = 1.f / fmaxf(sv, 1e-9f);
        for (int i = start; i < start + deg; ++i) {
            int src = g_srcs[i];
            float alpha = g_ws[(size_t)i * HH + h] * inv;
            float4 zv = *(const float4*)&g_z[(size_t)src * DD + lane * 4];
            acc.x = fmaf(alpha, zv.x, acc.x);
            acc.y = fmaf(alpha, zv.y, acc.y);
            acc.z = fmaf(alpha, zv.z, acc.z);
            acc.w = fmaf(alpha, zv.w, acc.w);
        }
    }
    *(float4*)&g_hagg[(size_t)n * DD + lane * 4] = acc;
}

// ---------------- elu + residual + LayerNorm (warp per node) ----------------
__global__ void ln_kernel(const float* __restrict__ x,
                          const float* __restrict__ gamma, const float* __restrict__ beta) {
    int warp = threadIdx.x >> 5;
    int lane = threadIdx.x & 31;
    int n = blockIdx.x * 8 + warp;
    if (n >= NN) return;
    float4 hv = ((const float4*)(g_hagg + n * DD))[lane];
    float4 xv = ((const float4*)(x + n * DD))[lane];
    float4 r;
    r.x = xv.x + (hv.x > 0.f ? hv.x : expm1f(hv.x));
    r.y = xv.y + (hv.y > 0.f ? hv.y : expm1f(hv.y));
    r.z = xv.z + (hv.z > 0.f ? hv.z : expm1f(hv.z));
    r.w = xv.w + (hv.w > 0.f ? hv.w : expm1f(hv.w));
    ((float4*)(g_hres + n * DD))[lane] = r;
    float sum = r.x + r.y + r.z + r.w;
    float sq = r.x * r.x + r.y * r.y + r.z * r.z + r.w * r.w;
#pragma unroll
    for (int o = 16; o >= 1; o >>= 1) {
        sum += __shfl_xor_sync(0xffffffffu, sum, o);
        sq  += __shfl_xor_sync(0xffffffffu, sq, o);
    }
    float mu = sum * (1.f / 128.f);
    float var = sq * (1.f / 128.f) - mu * mu;
    float rstd = rsqrtf(var + 1e-5f);
    float4 gv = ((const float4*)gamma)[lane];
    float4 bv = ((const float4*)beta)[lane];
    float4 o;
    o.x = (r.x - mu) * rstd * gv.x + bv.x;
    o.y = (r.y - mu) * rstd * gv.y + bv.y;
    o.z = (r.z - mu) * rstd * gv.z + bv.z;
    o.w = (r.w - mu) * rstd * gv.w + bv.w;
    ((float4*)(g_ln + n * DD))[lane] = o;
}

// ---------------- launch ----------------
extern "C" void kernel_launch(void* const* d_in, const int* in_sizes, int n_in,
                              void* d_out, int out_size) {
    const float* x      = (const float*)d_in[0];
    const float* wfc    = (const float*)d_in[1];
    const float* a_l    = (const float*)d_in[2];
    const float* a_r    = (const float*)d_in[3];
    const float* gamma  = (const float*)d_in[4];
    const float* beta   = (const float*)d_in[5];
    const float* W1     = (const float*)d_in[6];
    const float* b1     = (const float*)d_in[7];
    const float* W2     = (const float*)d_in[8];
    const float* b2     = (const float*)d_in[9];
    const int* esrc     = (const int*)d_in[10];
    const int* edst     = (const int*)d_in[11];
    float* out          = (float*)d_out;

    float *p_z, *p_wt, *p_ln, *p_inter, *p_hres;
    cudaGetSymbolAddress((void**)&p_z, g_z);
    cudaGetSymbolAddress((void**)&p_wt, g_wt);
    cudaGetSymbolAddress((void**)&p_ln, g_ln);
    cudaGetSymbolAddress((void**)&p_inter, g_inter);
    cudaGetSymbolAddress((void**)&p_hres, g_hres);

    zero_kernel<<<(NN + 255) / 256, 256>>>();
    transpose_wfc<<<(DD * DD + 255) / 256, 256>>>(wfc);

    // z = x @ WT
    {
        dim3 grid((NN + 127) / 128, 1);
        tgemm_kernel<0><<<grid, 256>>>(x, p_wt, p_z, NN, DD, DD, nullptr, nullptr);
    }
    eler_kernel<<<(NN * HH + 255) / 256, 256>>>(a_l, a_r);

    // CSR build
    deg_kernel<<<(EE + 255) / 256, 256>>>(edst);
    scan1_kernel<<<NBLK_SCAN, 256>>>();
    scan2_kernel<<<1, 256>>>();
    scan3_kernel<<<(NN + 255) / 256, 256>>>();
    scatter_kernel<<<(EE + 255) / 256, 256>>>(esrc, edst);

    agg_kernel<<<(NN + 7) / 8, 256>>>();
    ln_kernel<<<(NN + 7) / 8, 256>>>(x, gamma, beta);

    // inter = relu(ln @ W1 + b1)
    {
        dim3 grid((NN + 127) / 128, DFF / 128);
        tgemm_kernel<1><<<grid, 256>>>(p_ln, W1, p_inter, NN, DFF, DD, b1, nullptr);
    }
    // out = inter @ W2 + b2 + hres
    {
        dim3 grid((NN + 127) / 128, 1);
        tgemm_kernel<2><<<grid, 256>>>(p_inter, W2, out, NN, DD, DFF, b2, p_hres);
    }
}